// round 3
// baseline (speedup 1.0000x reference)
#include <cuda_runtime.h>

#define CI 64
#define DI 128
#define SS 16
#define RR 4
#define KK 4
#define HH 48
#define WW 48
#define LL 2304
#define TT 4
#define NCH 16
#define LCH 144
#define LOG2E 1.4426950408889634f

// ---------------- scratch (static device globals; no allocations) ----------------
__device__ float g_prev[CI*LL];
__device__ float g_cur [CI*LL];
__device__ float g_kl  [CI*LL];
__device__ float g_xln [TT*CI*LL];
__device__ float g_bias[TT*CI*LL];
__device__ float g_xz  [TT*2*DI*LL];
__device__ float g_xc  [TT*DI*LL];
__device__ float g_xcT [TT*DI*LL];
__device__ float g_dt  [TT*KK*DI*LL];
__device__ float g_Bt  [TT*KK*LL*SS];
__device__ float g_Ct  [TT*KK*LL*SS];
__device__ float g_y   [TT*KK*DI*LL];
__device__ float g_A   [2*KK*DI*SS];
__device__ float g_sumDs[2*DI];

// ---------------- precompute A = -exp(A_logs), sumDs ----------------
__global__ void k_precompute(const float* __restrict__ A_logs, const float* __restrict__ Ds){
    int i = blockIdx.x*blockDim.x + threadIdx.x;
    if (i < 2*KK*DI*SS) g_A[i] = -__expf(A_logs[i]);
    if (i < 2*DI){
        int m = i/DI, d = i%DI;
        float s = 0.f;
        #pragma unroll
        for (int k = 0; k < KK; k++) s += Ds[(m*KK+k)*DI + d];
        g_sumDs[i] = s;
    }
}

// ---------------- init (tiled, coalesced): prev=LN(dz), cur=prev*exp(sigma), xln[t]=LN(img[t]) ----
// grid 72 blocks of 32 pixels, 128 threads
__global__ void k_init(const float* __restrict__ dz, const float* __restrict__ sigma,
                       const float* __restrict__ img,
                       const float* __restrict__ niw, const float* __restrict__ nib,
                       const float* __restrict__ ndw, const float* __restrict__ ndb){
    __shared__ float sx[CI*33];
    __shared__ float smu[32], srs[32];
    int l0 = blockIdx.x*32, tid = threadIdx.x;

    // ---- dz -> prev, cur ----
    for (int j = tid; j < CI*32; j += 128){
        int c = j >> 5, li = j & 31;
        sx[c*33 + li] = dz[c*LL + l0 + li];
    }
    __syncthreads();
    if (tid < 32){
        float s0 = 0.f, s1 = 0.f;
        for (int c = 0; c < CI; c++){ float v = sx[c*33 + tid]; s0 += v; s1 += v*v; }
        float mu = s0*(1.f/CI);
        smu[tid] = mu;
        srs[tid] = rsqrtf(s1*(1.f/CI) - mu*mu + 1e-6f);
    }
    __syncthreads();
    for (int j = tid; j < CI*32; j += 128){
        int c = j >> 5, li = j & 31;
        float pv = (sx[c*33+li] - smu[li])*srs[li]*ndw[c] + ndb[c];
        g_prev[c*LL + l0 + li] = pv;
        g_cur [c*LL + l0 + li] = pv * __expf(sigma[c*LL + l0 + li]);
    }
    __syncthreads();

    // ---- img[t] -> xln[t] ----
    for (int t = 0; t < TT; t++){
        for (int j = tid; j < CI*32; j += 128){
            int c = j >> 5, li = j & 31;
            sx[c*33 + li] = img[(t*CI + c)*LL + l0 + li];
        }
        __syncthreads();
        if (tid < 32){
            float s0 = 0.f, s1 = 0.f;
            for (int c = 0; c < CI; c++){ float v = sx[c*33 + tid]; s0 += v; s1 += v*v; }
            float mu = s0*(1.f/CI);
            smu[tid] = mu;
            srs[tid] = rsqrtf(s1*(1.f/CI) - mu*mu + 1e-6f);
        }
        __syncthreads();
        for (int j = tid; j < CI*32; j += 128){
            int c = j >> 5, li = j & 31;
            g_xln[(t*CI + c)*LL + l0 + li] = (sx[c*33+li] - smu[li])*srs[li]*niw[c] + nib[c];
        }
        __syncthreads();
    }
}

// ---------------- KL(cur, prev) (tiled, coalesced) ----------------
__global__ void k_kl(){
    __shared__ float sp[CI*33], sq[CI*33];
    __shared__ float slp[32], slq[32];
    int l0 = blockIdx.x*32, tid = threadIdx.x;
    for (int j = tid; j < CI*32; j += 128){
        int c = j >> 5, li = j & 31;
        sp[c*33 + li] = g_prev[c*LL + l0 + li];
        sq[c*33 + li] = g_cur [c*LL + l0 + li];
    }
    __syncthreads();
    if (tid < 32){
        float mp = -1e30f, mq = -1e30f;
        for (int c = 0; c < CI; c++){
            mp = fmaxf(mp, sp[c*33 + tid]);
            mq = fmaxf(mq, sq[c*33 + tid]);
        }
        float ep = 0.f, eq = 0.f;
        for (int c = 0; c < CI; c++){
            ep += __expf(sp[c*33 + tid] - mp);
            eq += __expf(sq[c*33 + tid] - mq);
        }
        slp[tid] = mp + __logf(ep);
        slq[tid] = mq + __logf(eq);
    }
    __syncthreads();
    for (int j = tid; j < CI*32; j += 128){
        int c = j >> 5, li = j & 31;
        float lp = sp[c*33+li] - slp[li];
        float lq = sq[c*33+li] - slq[li];
        g_kl[c*LL + l0 + li] = __expf(lp)*(lp - lq);
    }
}

// ---------------- in-projection GEMM: xz[256,L] = W[256,64]@x[64,L]+b ----------------
__global__ void k_inproj(const float* __restrict__ in_w, const float* __restrict__ in_b,
                         int m, int srcsel){
    __shared__ float sx[64*128];
    __shared__ float swT[64*33];
    const int lt = blockIdx.x, dtile = blockIdx.y, b = blockIdx.z, tid = threadIdx.x;
    const float* src = (srcsel ? g_xln : g_kl) + b*CI*LL + lt*128;
    for (int j = tid; j < 64*128; j += 128){
        int c = j >> 7;
        sx[j] = src[c*LL + tid];
    }
    for (int j = tid; j < 32*64; j += 128){
        int dp = j >> 6, c = j & 63;
        swT[c*33 + dp] = __ldg(&in_w[(m*256 + dtile*32 + dp)*64 + c]);
    }
    __syncthreads();
    int lq = tid & 31, dq = tid >> 5;
    float acc[8][4];
    #pragma unroll
    for (int i = 0; i < 8; i++){
        float bb = __ldg(&in_b[m*256 + dtile*32 + dq*8 + i]);
        #pragma unroll
        for (int j = 0; j < 4; j++) acc[i][j] = bb;
    }
    #pragma unroll 4
    for (int c = 0; c < 64; c++){
        float4 xv = *(const float4*)&sx[c*128 + lq*4];
        float xa[4] = {xv.x, xv.y, xv.z, xv.w};
        float wv[8];
        #pragma unroll
        for (int i = 0; i < 8; i++) wv[i] = swT[c*33 + dq*8 + i];
        #pragma unroll
        for (int i = 0; i < 8; i++)
            #pragma unroll
            for (int j = 0; j < 4; j++) acc[i][j] += wv[i]*xa[j];
    }
    #pragma unroll
    for (int i = 0; i < 8; i++){
        int d = dtile*32 + dq*8 + i;
        float* o = g_xz + (b*2*DI + d)*LL + lt*128 + lq*4;
        *(float4*)o = make_float4(acc[i][0], acc[i][1], acc[i][2], acc[i][3]);
    }
}

// ---------------- depthwise 3x3 conv + bias + silu (smem-staged input) ----------------
__global__ void k_conv(const float* __restrict__ cw, const float* __restrict__ cb, int m){
    __shared__ float sin[LL];
    __shared__ float sc[48*49];
    int d = blockIdx.x, b = blockIdx.y, tid = threadIdx.x;
    const float* in = g_xz + (b*2*DI + d)*LL;
    for (int i = tid; i < LL; i += 256) sin[i] = in[i];
    float w9[9];
    #pragma unroll
    for (int j = 0; j < 9; j++) w9[j] = __ldg(&cw[(m*DI + d)*9 + j]);
    float bias = __ldg(&cb[m*DI + d]);
    __syncthreads();
    for (int i = tid; i < LL; i += 256){
        int h = i/48, w = i%48;
        float acc = 0.f;
        #pragma unroll
        for (int ky = 0; ky < 3; ky++){
            int hy = h + ky - 1;
            if (hy < 0 || hy >= 48) continue;
            #pragma unroll
            for (int kx = 0; kx < 3; kx++){
                int wx = w + kx - 1;
                if (wx < 0 || wx >= 48) continue;
                acc += w9[ky*3+kx] * sin[hy*48 + wx];
            }
        }
        acc += bias;
        acc = acc / (1.f + __expf(-acc));
        sc[h*49 + w] = acc;
    }
    __syncthreads();
    float* oc = g_xc  + (b*DI + d)*LL;
    float* ot = g_xcT + (b*DI + d)*LL;
    for (int i = tid; i < LL; i += 256){
        int h = i/48, w = i%48;
        oc[i] = sc[h*49 + w];
        ot[i] = sc[w*49 + h];
    }
}

// ---------------- x-projection + dt(softplus) + B/C transpose; grid(48,K,nb), block 192 ----------------
__global__ void k_xproj(const float* __restrict__ xpw, const float* __restrict__ dtw,
                        const float* __restrict__ dtb, int m){
    __shared__ float s1[DI*48];
    __shared__ float s2[36*DI];
    int lt = blockIdx.x, k = blockIdx.y, b = blockIdx.z, tid = threadIdx.x;
    bool fwd = (k < 2);
    const float* src = ((k & 1) ? g_xcT : g_xc) + b*DI*LL;
    for (int j = tid; j < DI*48; j += 192){
        int d = j/48, ls = j%48;
        int gl = fwd ? (lt*48 + ls) : (LL-1 - (lt*48 + ls));
        s1[j] = src[d*LL + gl];
    }
    const float* wk = xpw + (m*KK + k)*36*DI;
    for (int j = tid; j < 36*DI; j += 192) s2[j] = __ldg(&wk[j]);
    __syncthreads();
    int ls = tid % 48, rg = tid / 48;
    float acc[9];
    #pragma unroll
    for (int i = 0; i < 9; i++) acc[i] = 0.f;
    for (int c = 0; c < DI; c++){
        float xv = s1[c*48 + ls];
        #pragma unroll
        for (int i = 0; i < 9; i++) acc[i] += s2[(rg*9 + i)*DI + c] * xv;
    }
    __syncthreads();
    #pragma unroll
    for (int i = 0; i < 9; i++) s1[(rg*9 + i)*48 + ls] = acc[i];
    __syncthreads();
    const float* dwk = dtw + (m*KK + k)*DI*RR;
    const float* dbk = dtb + (m*KK + k)*DI;
    float* dto = g_dt + ((size_t)(b*KK + k)*DI)*LL + lt*48;
    #pragma unroll 4
    for (int i = 0; i < 32; i++){
        int d = rg + 4*i;
        float v = __ldg(&dbk[d]);
        #pragma unroll
        for (int r = 0; r < 4; r++) v += __ldg(&dwk[d*4 + r]) * s1[r*48 + ls];
        v = fmaxf(v, 0.f) + log1pf(__expf(-fabsf(v)));
        dto[d*LL + ls] = v;
    }
    float* bt = g_Bt + ((size_t)(b*KK + k)*LL + lt*48)*SS;
    float* ct = g_Ct + ((size_t)(b*KK + k)*LL + lt*48)*SS;
    for (int j = tid; j < 48*SS; j += 192){
        int lls = j/SS, s = j%SS;
        bt[lls*SS + s] = s1[(4 + s)*48 + lls];
        ct[lls*SS + s] = s1[(20 + s)*48 + lls];
    }
}

// ---------------- scan v2: single-exp-pass with w-memoization ----------------
// grid(DI,KK,nb), 256 threads = 16 s-lanes x 16 chunks of 144
// smem: w[l*17 + s] (s=16 slot holds yloc), pA[256], pH[256] -> 158,720 B dynamic
#define SCAN_SMEM_BYTES ((LL*17 + 512)*4)
__global__ __launch_bounds__(256) void k_scan(int m){
    extern __shared__ float sm[];
    float* w  = sm;                  // LL*17 floats
    float* pA = sm + LL*17;          // 256
    float* pH = pA + 256;            // 256
    int d = blockIdx.x, k = blockIdx.y, b = blockIdx.z, tid = threadIdx.x;
    int s = tid & 15, c = tid >> 4;
    bool fwd = (k < 2);
    const float* dtrow = g_dt + ((size_t)(b*KK + k)*DI + d)*LL;
    const float* xrow  = ((k & 1) ? g_xcT : g_xc) + (b*DI + d)*LL;
    const float* bt = g_Bt + ((size_t)(b*KK + k)*LL)*SS;
    const float* ct = g_Ct + ((size_t)(b*KK + k)*LL)*SS;
    float A2 = __ldg(&g_A[((m*KK + k)*DI + d)*SS + s]) * LOG2E;

    // pass 1: chunk-local scan; memoize w = C*prefixProd, yloc = sum_s C*h_local
    float ap = 1.f, h = 0.f;
    int l0 = c*LCH;
    #pragma unroll 4
    for (int i = 0; i < LCH; i++){
        int l = l0 + i;
        float dtv = __ldg(&dtrow[l]);                       // broadcast within group
        float xv  = fwd ? __ldg(&xrow[l]) : __ldg(&xrow[LL-1-l]);
        float da  = exp2f(A2 * dtv);
        ap *= da;
        float btv = __ldg(&bt[l*SS + s]);
        h = da*h + (dtv*xv)*btv;
        float ctv = __ldg(&ct[l*SS + s]);
        w[l*17 + s] = ctv * ap;
        float v = ctv * h;
        v += __shfl_xor_sync(0xffffffffu, v, 1);
        v += __shfl_xor_sync(0xffffffffu, v, 2);
        v += __shfl_xor_sync(0xffffffffu, v, 4);
        v += __shfl_xor_sync(0xffffffffu, v, 8);
        if (s == 0) w[l*17 + 16] = v;                       // yloc in pad slot
    }
    pA[tid] = ap; pH[tid] = h;
    __syncthreads();

    // pass 2: serial scan over 16 chunk summaries per state; pH becomes h-entering-chunk
    if (tid < 16){
        float hh = 0.f;
        #pragma unroll
        for (int cc = 0; cc < NCH; cc++){
            int idx = cc*16 + tid;
            float tmp = pH[idx];
            pH[idx] = hh;
            hh = pA[idx]*hh + tmp;
        }
    }
    __syncthreads();

    // pass 3: y_l = yloc_l + sum_s w[l][s]*hI[s]  (pure dot, transposed lanes, no exp)
    float hreg[17];
    #pragma unroll
    for (int s2 = 0; s2 < 16; s2++) hreg[s2] = pH[c*16 + s2];
    hreg[16] = 1.f;
    float* yrow = g_y + ((size_t)(b*KK + k)*DI + d)*LL;
    #pragma unroll
    for (int j = 0; j < 9; j++){
        int l = l0 + s + 16*j;
        float acc = 0.f;
        #pragma unroll
        for (int s2 = 0; s2 < 17; s2++) acc += w[l*17 + s2]*hreg[s2];
        yrow[fwd ? l : (LL-1-l)] = acc;
    }
}

// ---------------- merge dirs + LN + silu(z) gate + out-proj + (recurrent update) ----------------
__global__ void k_merge(const float* __restrict__ onw, const float* __restrict__ onb,
                        const float* __restrict__ ow,  const float* __restrict__ ob,
                        int m, int mode, int t, float* __restrict__ outp){
    __shared__ float syy[DI*32];
    __shared__ float red0[8*32], red1[8*32];
    int tid = threadIdx.x;
    int lsub = tid & 31, dg = tid >> 5;
    int b = blockIdx.y;
    int l = blockIdx.x*32 + lsub;
    int tl = (l % 48)*48 + l/48;
    float ps = 0.f, pq = 0.f;
    for (int i = 0; i < 16; i++){
        int d = dg*16 + i;
        const float* y0 = g_y + ((size_t)(b*KK + 0)*DI + d)*LL;
        const float* y1 = g_y + ((size_t)(b*KK + 1)*DI + d)*LL;
        const float* y2 = g_y + ((size_t)(b*KK + 2)*DI + d)*LL;
        const float* y3 = g_y + ((size_t)(b*KK + 3)*DI + d)*LL;
        float v = y0[l] + y2[l] + y1[tl] + y3[tl]
                + g_sumDs[m*DI + d] * g_xc[(b*DI + d)*LL + l];
        syy[d*32 + lsub] = v;
        ps += v; pq += v*v;
    }
    red0[dg*32 + lsub] = ps; red1[dg*32 + lsub] = pq;
    __syncthreads();
    if (dg == 0){
        float s0 = 0.f, s1 = 0.f;
        #pragma unroll
        for (int j = 0; j < 8; j++){ s0 += red0[j*32 + lsub]; s1 += red1[j*32 + lsub]; }
        float mu  = s0 * (1.f/DI);
        float var = s1 * (1.f/DI) - mu*mu;
        red0[lsub] = mu;
        red1[lsub] = rsqrtf(var + 1e-6f);
    }
    __syncthreads();
    float mu = red0[lsub], rs = red1[lsub];
    for (int i = 0; i < 16; i++){
        int d = dg*16 + i;
        float v  = syy[d*32 + lsub];
        float wn = (v - mu)*rs*__ldg(&onw[m*DI + d]) + __ldg(&onb[m*DI + d]);
        float z  = g_xz[(b*2*DI + DI + d)*LL + l];
        float sz = z / (1.f + __expf(-z));
        syy[d*32 + lsub] = wn * sz;
    }
    __syncthreads();
    int cg = dg;
    float acc[8];
    #pragma unroll
    for (int i = 0; i < 8; i++) acc[i] = __ldg(&ob[m*CI + cg*8 + i]);
    for (int d = 0; d < DI; d++){
        float v = syy[d*32 + lsub];
        #pragma unroll
        for (int i = 0; i < 8; i++) acc[i] += __ldg(&ow[(m*CI + cg*8 + i)*DI + d]) * v;
    }
    #pragma unroll
    for (int i = 0; i < 8; i++){
        int cc = cg*8 + i;
        if (mode == 1){
            g_bias[(b*CI + cc)*LL + l] = acc[i];
        } else {
            int idx = cc*LL + l;
            float co = g_cur[idx];
            g_prev[idx] = co;
            float nv = co * __expf(acc[i]) + g_bias[(t*CI + cc)*LL + l];
            g_cur[idx] = nv;
            if (outp) outp[idx] = nv;
        }
    }
}

// ---------------- launch ----------------
extern "C" void kernel_launch(void* const* d_in, const int* in_sizes, int n_in,
                              void* d_out, int out_size){
    const float* img    = (const float*)d_in[0];
    const float* dz     = (const float*)d_in[1];
    const float* sigma  = (const float*)d_in[2];
    const float* in_w   = (const float*)d_in[3];
    const float* in_b   = (const float*)d_in[4];
    const float* conv_w = (const float*)d_in[5];
    const float* conv_b = (const float*)d_in[6];
    const float* xp_w   = (const float*)d_in[7];
    const float* dt_w   = (const float*)d_in[8];
    const float* dt_b   = (const float*)d_in[9];
    const float* A_logs = (const float*)d_in[10];
    const float* Ds     = (const float*)d_in[11];
    const float* onw    = (const float*)d_in[12];
    const float* onb    = (const float*)d_in[13];
    const float* ow     = (const float*)d_in[14];
    const float* ob     = (const float*)d_in[15];
    const float* niw    = (const float*)d_in[16];
    const float* nib    = (const float*)d_in[17];
    const float* ndw    = (const float*)d_in[18];
    const float* ndb    = (const float*)d_in[19];
    float* outp = (float*)d_out;

    cudaFuncSetAttribute(k_scan, cudaFuncAttributeMaxDynamicSharedMemorySize, SCAN_SMEM_BYTES);

    k_precompute<<<64, 256>>>(A_logs, Ds);
    k_init<<<72, 128>>>(dz, sigma, img, niw, nib, ndw, ndb);

    // bias pipeline, all 4 frames batched (m = 1)
    k_inproj<<<dim3(18, 8, TT), 128>>>(in_w, in_b, 1, 1);
    k_conv  <<<dim3(DI, TT), 256>>>(conv_w, conv_b, 1);
    k_xproj <<<dim3(48, KK, TT), 192>>>(xp_w, dt_w, dt_b, 1);
    k_scan  <<<dim3(DI, KK, TT), 256, SCAN_SMEM_BYTES>>>(1);
    k_merge <<<dim3(72, TT), 256>>>(onw, onb, ow, ob, 1, 1, 0, nullptr);

    // sequential recurrence (m = 0)
    for (int t = 0; t < TT; t++){
        k_kl    <<<72, 128>>>();
        k_inproj<<<dim3(18, 8, 1), 128>>>(in_w, in_b, 0, 0);
        k_conv  <<<dim3(DI, 1), 256>>>(conv_w, conv_b, 0);
        k_xproj <<<dim3(48, KK, 1), 192>>>(xp_w, dt_w, dt_b, 0);
        k_scan  <<<dim3(DI, KK, 1), 256, SCAN_SMEM_BYTES>>>(0);
        k_merge <<<dim3(72, 1), 256>>>(onw, onb, ow, ob, 0, 0, t,
                                       (t == TT-1) ? outp : nullptr);
    }
}

// round 4
// speedup vs baseline: 2.1903x; 2.1903x over previous
#include <cuda_runtime.h>

#define CI 64
#define DI 128
#define SS 16
#define RR 4
#define KK 4
#define HH 48
#define WW 48
#define LL 2304
#define TT 4
#define NB 5          // slices: 0..3 = bias frames, 4 = sequential pipeline
#define SB 4
#define NCH 16
#define LCH 144

// ---------------- scratch (static device globals; no allocations) ----------------
__device__ float g_prev[CI*LL];
__device__ float g_cur [CI*LL];
__device__ float g_kl  [CI*LL];
__device__ float g_xln [TT*CI*LL];
__device__ float g_bias[TT*CI*LL];
__device__ float g_xz  [NB*2*DI*LL];
__device__ float g_xc  [NB*DI*LL];
__device__ float g_xcT [NB*DI*LL];
__device__ float g_dt  [NB*KK*DI*LL];
__device__ float g_Bt  [NB*KK*LL*SS];
__device__ float g_Ct  [NB*KK*LL*SS];
__device__ float g_y   [NB*KK*DI*LL];
__device__ float g_A   [2*KK*DI*SS];
__device__ float g_sumDs[2*DI];

// ---------------- precompute A = -exp(A_logs), sumDs ----------------
__global__ void k_precompute(const float* __restrict__ A_logs, const float* __restrict__ Ds){
    int i = blockIdx.x*blockDim.x + threadIdx.x;
    if (i < 2*KK*DI*SS) g_A[i] = -__expf(A_logs[i]);
    if (i < 2*DI){
        int m = i/DI, d = i%DI;
        float s = 0.f;
        #pragma unroll
        for (int k = 0; k < KK; k++) s += Ds[(m*KK+k)*DI + d];
        g_sumDs[i] = s;
    }
}

// ---------------- init: prev=LN(dz), cur=prev*exp(sigma), kl(t=0), xln[t]=LN(img[t]) ----------
// grid 72 blocks of 32 pixels, 128 threads
__global__ void k_init(const float* __restrict__ dz, const float* __restrict__ sigma,
                       const float* __restrict__ img,
                       const float* __restrict__ niw, const float* __restrict__ nib,
                       const float* __restrict__ ndw, const float* __restrict__ ndb){
    __shared__ float sx[CI*33];
    __shared__ float scur[CI*33];
    __shared__ float smu[32], srs[32], slp[32], slq[32];
    int l0 = blockIdx.x*32, tid = threadIdx.x;

    // ---- dz -> prev, cur ----
    for (int j = tid; j < CI*32; j += 128){
        int c = j >> 5, li = j & 31;
        sx[c*33 + li] = dz[c*LL + l0 + li];
    }
    __syncthreads();
    if (tid < 32){
        float s0 = 0.f, s1 = 0.f;
        for (int c = 0; c < CI; c++){ float v = sx[c*33 + tid]; s0 += v; s1 += v*v; }
        float mu = s0*(1.f/CI);
        smu[tid] = mu;
        srs[tid] = rsqrtf(s1*(1.f/CI) - mu*mu + 1e-6f);
    }
    __syncthreads();
    for (int j = tid; j < CI*32; j += 128){
        int c = j >> 5, li = j & 31;
        float pv = (sx[c*33+li] - smu[li])*srs[li]*ndw[c] + ndb[c];
        float cv = pv * __expf(sigma[c*LL + l0 + li]);
        g_prev[c*LL + l0 + li] = pv;
        g_cur [c*LL + l0 + li] = cv;
        sx  [c*33 + li] = pv;
        scur[c*33 + li] = cv;
    }
    __syncthreads();
    // ---- kl for t=0: kl = exp(lp)*(lp - lq), lp = p - lse(p), lq = q - lse(q) ----
    if (tid < 32){
        float mp = -1e30f, mq = -1e30f;
        for (int c = 0; c < CI; c++){
            mp = fmaxf(mp, sx  [c*33 + tid]);
            mq = fmaxf(mq, scur[c*33 + tid]);
        }
        float ep = 0.f, eq = 0.f;
        for (int c = 0; c < CI; c++){
            ep += __expf(sx  [c*33 + tid] - mp);
            eq += __expf(scur[c*33 + tid] - mq);
        }
        slp[tid] = mp + __logf(ep);
        slq[tid] = mq + __logf(eq);
    }
    __syncthreads();
    for (int j = tid; j < CI*32; j += 128){
        int c = j >> 5, li = j & 31;
        float lp = sx  [c*33+li] - slp[li];
        float lq = scur[c*33+li] - slq[li];
        g_kl[c*LL + l0 + li] = __expf(lp)*(lp - lq);
    }
    __syncthreads();

    // ---- img[t] -> xln[t] ----
    for (int t = 0; t < TT; t++){
        for (int j = tid; j < CI*32; j += 128){
            int c = j >> 5, li = j & 31;
            sx[c*33 + li] = img[(t*CI + c)*LL + l0 + li];
        }
        __syncthreads();
        if (tid < 32){
            float s0 = 0.f, s1 = 0.f;
            for (int c = 0; c < CI; c++){ float v = sx[c*33 + tid]; s0 += v; s1 += v*v; }
            float mu = s0*(1.f/CI);
            smu[tid] = mu;
            srs[tid] = rsqrtf(s1*(1.f/CI) - mu*mu + 1e-6f);
        }
        __syncthreads();
        for (int j = tid; j < CI*32; j += 128){
            int c = j >> 5, li = j & 31;
            g_xln[(t*CI + c)*LL + l0 + li] = (sx[c*33+li] - smu[li])*srs[li]*niw[c] + nib[c];
        }
        __syncthreads();
    }
}

// ---------------- in-projection GEMM: xz[256,L] = W[256,64]@x[64,L]+b ----------------
// grid(18 ltiles, 8 dtiles, nframes), block 128
__global__ void k_inproj(const float* __restrict__ in_w, const float* __restrict__ in_b,
                         int m, int srcsel, int bofs){
    __shared__ float sx[64*128];
    __shared__ float swT[64*33];
    const int lt = blockIdx.x, dtile = blockIdx.y, fb = blockIdx.z, tid = threadIdx.x;
    const int slice = fb + bofs;
    const float* src = (srcsel ? (g_xln + fb*CI*LL) : g_kl) + lt*128;
    for (int j = tid; j < 64*128; j += 128){
        int c = j >> 7;
        sx[j] = src[c*LL + tid];
    }
    for (int j = tid; j < 32*64; j += 128){
        int dp = j >> 6, c = j & 63;
        swT[c*33 + dp] = __ldg(&in_w[(m*256 + dtile*32 + dp)*64 + c]);
    }
    __syncthreads();
    int lq = tid & 31, dq = tid >> 5;
    float acc[8][4];
    #pragma unroll
    for (int i = 0; i < 8; i++){
        float bb = __ldg(&in_b[m*256 + dtile*32 + dq*8 + i]);
        #pragma unroll
        for (int j = 0; j < 4; j++) acc[i][j] = bb;
    }
    #pragma unroll 4
    for (int c = 0; c < 64; c++){
        float4 xv = *(const float4*)&sx[c*128 + lq*4];
        float xa[4] = {xv.x, xv.y, xv.z, xv.w};
        float wv[8];
        #pragma unroll
        for (int i = 0; i < 8; i++) wv[i] = swT[c*33 + dq*8 + i];
        #pragma unroll
        for (int i = 0; i < 8; i++)
            #pragma unroll
            for (int j = 0; j < 4; j++) acc[i][j] += wv[i]*xa[j];
    }
    #pragma unroll
    for (int i = 0; i < 8; i++){
        int d = dtile*32 + dq*8 + i;
        float* o = g_xz + (slice*2*DI + d)*LL + lt*128 + lq*4;
        *(float4*)o = make_float4(acc[i][0], acc[i][1], acc[i][2], acc[i][3]);
    }
}

// ---------------- depthwise 3x3 conv + bias + silu (smem-staged) ----------------
__global__ void k_conv(const float* __restrict__ cw, const float* __restrict__ cb,
                       int m, int bofs){
    __shared__ float sin[LL];
    __shared__ float sc[48*49];
    int d = blockIdx.x, slice = blockIdx.y + bofs, tid = threadIdx.x;
    const float* in = g_xz + (slice*2*DI + d)*LL;
    for (int i = tid; i < LL; i += 256) sin[i] = in[i];
    float w9[9];
    #pragma unroll
    for (int j = 0; j < 9; j++) w9[j] = __ldg(&cw[(m*DI + d)*9 + j]);
    float bias = __ldg(&cb[m*DI + d]);
    __syncthreads();
    for (int i = tid; i < LL; i += 256){
        int h = i/48, w = i%48;
        float acc = 0.f;
        #pragma unroll
        for (int ky = 0; ky < 3; ky++){
            int hy = h + ky - 1;
            if (hy < 0 || hy >= 48) continue;
            #pragma unroll
            for (int kx = 0; kx < 3; kx++){
                int wx = w + kx - 1;
                if (wx < 0 || wx >= 48) continue;
                acc += w9[ky*3+kx] * sin[hy*48 + wx];
            }
        }
        acc += bias;
        acc = acc / (1.f + __expf(-acc));
        sc[h*49 + w] = acc;
    }
    __syncthreads();
    float* oc = g_xc  + (slice*DI + d)*LL;
    float* ot = g_xcT + (slice*DI + d)*LL;
    for (int i = tid; i < LL; i += 256){
        int h = i/48, w = i%48;
        oc[i] = sc[h*49 + w];
        ot[i] = sc[w*49 + h];
    }
}

// ---------------- x-projection + dt(softplus) + B/C transpose; grid(48,K,nf), block 192 ----------------
__global__ void k_xproj(const float* __restrict__ xpw, const float* __restrict__ dtw,
                        const float* __restrict__ dtb, int m, int bofs){
    __shared__ float s1[DI*48];
    __shared__ float s2[36*DI];
    int lt = blockIdx.x, k = blockIdx.y, slice = blockIdx.z + bofs, tid = threadIdx.x;
    bool fwd = (k < 2);
    const float* src = ((k & 1) ? g_xcT : g_xc) + slice*DI*LL;
    for (int j = tid; j < DI*48; j += 192){
        int d = j/48, ls = j%48;
        int gl = fwd ? (lt*48 + ls) : (LL-1 - (lt*48 + ls));
        s1[j] = src[d*LL + gl];
    }
    const float* wk = xpw + (m*KK + k)*36*DI;
    for (int j = tid; j < 36*DI; j += 192) s2[j] = __ldg(&wk[j]);
    __syncthreads();
    int ls = tid % 48, rg = tid / 48;
    float acc[9];
    #pragma unroll
    for (int i = 0; i < 9; i++) acc[i] = 0.f;
    for (int c = 0; c < DI; c++){
        float xv = s1[c*48 + ls];
        #pragma unroll
        for (int i = 0; i < 9; i++) acc[i] += s2[(rg*9 + i)*DI + c] * xv;
    }
    __syncthreads();
    #pragma unroll
    for (int i = 0; i < 9; i++) s1[(rg*9 + i)*48 + ls] = acc[i];
    __syncthreads();
    const float* dwk = dtw + (m*KK + k)*DI*RR;
    const float* dbk = dtb + (m*KK + k)*DI;
    float* dto = g_dt + ((size_t)(slice*KK + k)*DI)*LL + lt*48;
    #pragma unroll 4
    for (int i = 0; i < 32; i++){
        int d = rg + 4*i;
        float v = __ldg(&dbk[d]);
        #pragma unroll
        for (int r = 0; r < 4; r++) v += __ldg(&dwk[d*4 + r]) * s1[r*48 + ls];
        v = fmaxf(v, 0.f) + log1pf(__expf(-fabsf(v)));
        dto[d*LL + ls] = v;
    }
    float* bt = g_Bt + ((size_t)(slice*KK + k)*LL + lt*48)*SS;
    float* ct = g_Ct + ((size_t)(slice*KK + k)*LL + lt*48)*SS;
    for (int j = tid; j < 48*SS; j += 192){
        int lls = j/SS, s = j%SS;
        bt[lls*SS + s] = s1[(4 + s)*48 + lls];
        ct[lls*SS + s] = s1[(20 + s)*48 + lls];
    }
}

// ---------------- chunked scan + y = sum_s h*C (R2 proven form); grid(DI,KK,nf), 256 thr ----------------
__global__ void k_scan(int m, int bofs){
    __shared__ float sdt [LL];
    __shared__ float sdtx[LL];
    __shared__ float pA[256], pH[256], hI[256];
    int d = blockIdx.x, k = blockIdx.y, slice = blockIdx.z + bofs, tid = threadIdx.x;
    int s = tid & 15, c = tid >> 4;
    const float* dtrow = g_dt + ((size_t)(slice*KK + k)*DI + d)*LL;
    const float* xrow  = ((k & 1) ? g_xcT : g_xc) + (slice*DI + d)*LL;
    bool fwd = (k < 2);
    for (int i = tid; i < LL; i += 256){
        float dv = dtrow[i];
        float xv = fwd ? xrow[i] : xrow[LL-1-i];
        sdt[i]  = dv;
        sdtx[i] = dv * xv;
    }
    __syncthreads();
    float Av = __ldg(&g_A[((m*KK + k)*DI + d)*SS + s]);
    const float* bt = g_Bt + ((size_t)(slice*KK + k)*LL)*SS;
    const float* ct = g_Ct + ((size_t)(slice*KK + k)*LL)*SS;
    // pass 1: chunk-local (aProd, hEnd)
    float ap = 1.f, h = 0.f;
    int l0 = c*LCH;
    #pragma unroll 4
    for (int i = 0; i < LCH; i++){
        int l = l0 + i;
        float da = __expf(Av * sdt[l]);
        ap *= da;
        h = da*h + sdtx[l] * __ldg(&bt[l*SS + s]);
    }
    pA[tid] = ap; pH[tid] = h;
    __syncthreads();
    // pass 2: serial scan over 16 chunk summaries (one thread per s)
    if (tid < 16){
        float hh = 0.f;
        #pragma unroll
        for (int cc = 0; cc < NCH; cc++){
            hI[cc*16 + tid] = hh;
            hh = pA[cc*16 + tid]*hh + pH[cc*16 + tid];
        }
    }
    __syncthreads();
    // pass 3: recompute with true h_init, reduce over s, write y
    h = hI[tid];
    float* yrow = g_y + ((size_t)(slice*KK + k)*DI + d)*LL;
    #pragma unroll 2
    for (int i = 0; i < LCH; i++){
        int l = l0 + i;
        float da = __expf(Av * sdt[l]);
        h = da*h + sdtx[l] * __ldg(&bt[l*SS + s]);
        float v = h * __ldg(&ct[l*SS + s]);
        v += __shfl_xor_sync(0xffffffffu, v, 1);
        v += __shfl_xor_sync(0xffffffffu, v, 2);
        v += __shfl_xor_sync(0xffffffffu, v, 4);
        v += __shfl_xor_sync(0xffffffffu, v, 8);
        if (s == 0){
            int ol = fwd ? l : (LL-1-l);
            yrow[ol] = v;
        }
    }
}

// ---------------- merge + LN + gate + out-proj + recurrent update + next-step KL ----------------
// grid(72, nf), block 256 = 32 lsub x 8 dg
__global__ void k_merge(const float* __restrict__ onw, const float* __restrict__ onb,
                        const float* __restrict__ ow,  const float* __restrict__ ob,
                        int m, int mode, int t, int bofs, int doKL,
                        float* __restrict__ outp){
    __shared__ float syy[DI*32];
    __shared__ float red0[8*32], red1[8*32];
    int tid = threadIdx.x;
    int lsub = tid & 31, dg = tid >> 5;
    int fb = blockIdx.y, slice = fb + bofs;
    int l = blockIdx.x*32 + lsub;
    int tl = (l % 48)*48 + l/48;
    float ps = 0.f, pq = 0.f;
    for (int i = 0; i < 16; i++){
        int d = dg*16 + i;
        const float* y0 = g_y + ((size_t)(slice*KK + 0)*DI + d)*LL;
        const float* y1 = g_y + ((size_t)(slice*KK + 1)*DI + d)*LL;
        const float* y2 = g_y + ((size_t)(slice*KK + 2)*DI + d)*LL;
        const float* y3 = g_y + ((size_t)(slice*KK + 3)*DI + d)*LL;
        float v = y0[l] + y2[l] + y1[tl] + y3[tl]
                + g_sumDs[m*DI + d] * g_xc[(slice*DI + d)*LL + l];
        syy[d*32 + lsub] = v;
        ps += v; pq += v*v;
    }
    red0[dg*32 + lsub] = ps; red1[dg*32 + lsub] = pq;
    __syncthreads();
    if (dg == 0){
        float s0 = 0.f, s1 = 0.f;
        #pragma unroll
        for (int j = 0; j < 8; j++){ s0 += red0[j*32 + lsub]; s1 += red1[j*32 + lsub]; }
        float mu  = s0 * (1.f/DI);
        float var = s1 * (1.f/DI) - mu*mu;
        red0[lsub] = mu;
        red1[lsub] = rsqrtf(var + 1e-6f);
    }
    __syncthreads();
    float mu = red0[lsub], rs = red1[lsub];
    for (int i = 0; i < 16; i++){
        int d = dg*16 + i;
        float v  = syy[d*32 + lsub];
        float wn = (v - mu)*rs*__ldg(&onw[m*DI + d]) + __ldg(&onb[m*DI + d]);
        float z  = g_xz[(slice*2*DI + DI + d)*LL + l];
        float sz = z / (1.f + __expf(-z));
        syy[d*32 + lsub] = wn * sz;
    }
    __syncthreads();
    int cg = dg;
    float acc[8];
    #pragma unroll
    for (int i = 0; i < 8; i++) acc[i] = __ldg(&ob[m*CI + cg*8 + i]);
    for (int d = 0; d < DI; d++){
        float v = syy[d*32 + lsub];
        #pragma unroll
        for (int i = 0; i < 8; i++) acc[i] += __ldg(&ow[(m*CI + cg*8 + i)*DI + d]) * v;
    }
    if (mode == 1){
        #pragma unroll
        for (int i = 0; i < 8; i++)
            g_bias[(fb*CI + cg*8 + i)*LL + l] = acc[i];
        return;
    }
    // recurrent update: prev = cur; cur = cur*exp(s) + bias[t]
    float co[8], nv[8];
    #pragma unroll
    for (int i = 0; i < 8; i++){
        int cc = cg*8 + i;
        int idx = cc*LL + l;
        co[i] = g_cur[idx];
        g_prev[idx] = co[i];
        nv[i] = co[i] * __expf(acc[i]) + g_bias[(t*CI + cc)*LL + l];
        g_cur[idx] = nv[i];
        if (outp) outp[idx] = nv[i];
    }
    if (!doKL) return;
    // next-step KL(cur_new, prev_new=co) computed in-place: reuse syy
    __syncthreads();           // all out-proj reads of syy complete
    #pragma unroll
    for (int i = 0; i < 8; i++){
        int cc = cg*8 + i;
        syy[cc*32 + lsub]        = co[i];   // prev
        syy[2048 + cc*32 + lsub] = nv[i];   // cur
    }
    __syncthreads();
    if (tid < 32){
        float mp = -1e30f, mq = -1e30f;
        for (int cc = 0; cc < CI; cc++){
            mp = fmaxf(mp, syy[cc*32 + tid]);
            mq = fmaxf(mq, syy[2048 + cc*32 + tid]);
        }
        float ep = 0.f, eq = 0.f;
        for (int cc = 0; cc < CI; cc++){
            ep += __expf(syy[cc*32 + tid] - mp);
            eq += __expf(syy[2048 + cc*32 + tid] - mq);
        }
        red0[tid] = mp + __logf(ep);
        red1[tid] = mq + __logf(eq);
    }
    __syncthreads();
    float lsep = red0[lsub], lseq = red1[lsub];
    #pragma unroll
    for (int i = 0; i < 8; i++){
        int cc = cg*8 + i;
        float lp = syy[cc*32 + lsub] - lsep;
        float lq = syy[2048 + cc*32 + lsub] - lseq;
        g_kl[cc*LL + l] = __expf(lp)*(lp - lq);
    }
}

// ---------------- launch ----------------
extern "C" void kernel_launch(void* const* d_in, const int* in_sizes, int n_in,
                              void* d_out, int out_size){
    const float* img    = (const float*)d_in[0];
    const float* dz     = (const float*)d_in[1];
    const float* sigma  = (const float*)d_in[2];
    const float* in_w   = (const float*)d_in[3];
    const float* in_b   = (const float*)d_in[4];
    const float* conv_w = (const float*)d_in[5];
    const float* conv_b = (const float*)d_in[6];
    const float* xp_w   = (const float*)d_in[7];
    const float* dt_w   = (const float*)d_in[8];
    const float* dt_b   = (const float*)d_in[9];
    const float* A_logs = (const float*)d_in[10];
    const float* Ds     = (const float*)d_in[11];
    const float* onw    = (const float*)d_in[12];
    const float* onb    = (const float*)d_in[13];
    const float* ow     = (const float*)d_in[14];
    const float* ob     = (const float*)d_in[15];
    const float* niw    = (const float*)d_in[16];
    const float* nib    = (const float*)d_in[17];
    const float* ndw    = (const float*)d_in[18];
    const float* ndb    = (const float*)d_in[19];
    float* outp = (float*)d_out;

    // fork/join stream for the independent bias pipeline (fallback: same stream)
    cudaStream_t s2 = 0;
    cudaEvent_t evF = 0, evJ = 0;
    bool fork = (cudaStreamCreateWithFlags(&s2, cudaStreamNonBlocking) == cudaSuccess);
    if (fork) fork = (cudaEventCreateWithFlags(&evF, cudaEventDisableTiming) == cudaSuccess);
    if (fork) fork = (cudaEventCreateWithFlags(&evJ, cudaEventDisableTiming) == cudaSuccess);
    cudaStream_t sb = fork ? s2 : (cudaStream_t)0;

    k_precompute<<<64, 256>>>(A_logs, Ds);
    k_init<<<72, 128>>>(dz, sigma, img, niw, nib, ndw, ndb);

    if (fork){
        cudaEventRecord(evF, 0);
        cudaStreamWaitEvent(s2, evF, 0);
    }

    // bias pipeline, all 4 frames batched (m = 1), slices 0..3
    k_inproj<<<dim3(18, 8, TT), 128, 0, sb>>>(in_w, in_b, 1, 1, 0);
    k_conv  <<<dim3(DI, TT), 256, 0, sb>>>(conv_w, conv_b, 1, 0);
    k_xproj <<<dim3(48, KK, TT), 192, 0, sb>>>(xp_w, dt_w, dt_b, 1, 0);
    k_scan  <<<dim3(DI, KK, TT), 256, 0, sb>>>(1, 0);
    k_merge <<<dim3(72, TT), 256, 0, sb>>>(onw, onb, ow, ob, 1, 1, 0, 0, 0, nullptr);

    if (fork) cudaEventRecord(evJ, s2);

    // sequential recurrence (m = 0), slice 4; KL produced by previous merge / init
    for (int t = 0; t < TT; t++){
        k_inproj<<<dim3(18, 8, 1), 128>>>(in_w, in_b, 0, 0, SB);
        k_conv  <<<dim3(DI, 1), 256>>>(conv_w, conv_b, 0, SB);
        k_xproj <<<dim3(48, KK, 1), 192>>>(xp_w, dt_w, dt_b, 0, SB);
        k_scan  <<<dim3(DI, KK, 1), 256>>>(0, SB);
        if (fork && t == 0) cudaStreamWaitEvent((cudaStream_t)0, evJ, 0);
        k_merge <<<dim3(72, 1), 256>>>(onw, onb, ow, ob, 0, 0, t, SB,
                                       (t < TT-1) ? 1 : 0,
                                       (t == TT-1) ? outp : nullptr);
    }
}